// round 1
// baseline (speedup 1.0000x reference)
#include <cuda_runtime.h>

// ---------------------------------------------------------------------------
// ExtractNet: fused multi-gate MoE, fp32, packed f32x2 FFMA path (sm_103a).
// B=65536, IN=256, H1=H2=OUT=64, T=2 tasks, ET=4 task experts/task, ES=4 shared.
// One CTA = 64 batch rows, fully fused: X tile -> gates -> 12 experts (pairs)
// -> gated accumulation -> single writeback. X is read from HBM exactly once.
// ---------------------------------------------------------------------------

#define M_TILE   64
#define NTHREADS 256
#define SX_LDA   260   // 256 + 4 pad (keeps 16B alignment, breaks bank conflicts)
#define SH_LDA   132   // 128 + 4 pad

typedef unsigned long long ull;

__device__ __forceinline__ ull fma2(ull a, ull b, ull c) {
    ull d;
    asm("fma.rn.f32x2 %0, %1, %2, %3;" : "=l"(d) : "l"(a), "l"(b), "l"(c));
    return d;
}
__device__ __forceinline__ ull pack2(float x) {
    ull d;
    asm("mov.b64 %0, {%1, %2};" : "=l"(d) : "f"(x), "f"(x));
    return d;
}
__device__ __forceinline__ void unpack2(ull v, float& lo, float& hi) {
    asm("mov.b64 {%0, %1}, %2;" : "=f"(lo), "=f"(hi) : "l"(v));
}

// 64-deep K block: acc[4 rows][4 packed col-pairs] += A[64r x 64k] * W[64k x 128c]
__device__ __forceinline__ void mm_block(const float* __restrict__ sA, int lda,
                                         const float* __restrict__ sWp,
                                         int r0, int c0, ull acc[4][4]) {
    #pragma unroll 8
    for (int k = 0; k < 64; k++) {
        ulonglong2 wA = *(const ulonglong2*)(sWp + k * 128 + c0);
        ulonglong2 wB = *(const ulonglong2*)(sWp + k * 128 + c0 + 4);
        ull w0 = wA.x, w1 = wA.y, w2 = wB.x, w3 = wB.y;
        #pragma unroll
        for (int i = 0; i < 4; i++) {
            ull a2 = pack2(sA[(r0 + i) * lda + k]);
            acc[i][0] = fma2(a2, w0, acc[i][0]);
            acc[i][1] = fma2(a2, w1, acc[i][1]);
            acc[i][2] = fma2(a2, w2, acc[i][2]);
            acc[i][3] = fma2(a2, w3, acc[i][3]);
        }
    }
}

// Stage an expert-pair weight block [64k x 128c] from two [64k x 64c] sources.
__device__ __forceinline__ void stage_w(float* __restrict__ sW,
                                        const float* __restrict__ Wa,
                                        const float* __restrict__ Wb, int tid) {
    #pragma unroll
    for (int i = 0; i < 8; i++) {
        int q  = tid + i * NTHREADS;   // float4 index, 2048 total
        int k  = q >> 5;
        int c4 = q & 31;
        const float4* src = (c4 < 16)
            ? (const float4*)(Wa + k * 64 + c4 * 4)
            : (const float4*)(Wb + k * 64 + (c4 - 16) * 4);
        *(float4*)(sW + k * 128 + c4 * 4) = *src;
    }
}

// bias + relu -> padded hidden buffer (transput for the next layer)
__device__ __forceinline__ void epi_relu(ull acc[4][4], const float* __restrict__ sB,
                                         float* __restrict__ sH, int r0, int c0) {
    #pragma unroll
    for (int i = 0; i < 4; i++) {
        #pragma unroll
        for (int j = 0; j < 4; j++) {
            float lo, hi;
            unpack2(acc[i][j], lo, hi);
            int c = c0 + 2 * j;
            lo = fmaxf(lo + sB[c], 0.f);
            hi = fmaxf(hi + sB[c + 1], 0.f);
            *(float2*)(sH + (r0 + i) * SH_LDA + c) = make_float2(lo, hi);
        }
    }
}

__device__ __forceinline__ void accum_out(ull acc[4][4], const float* __restrict__ sB3,
                                          float* __restrict__ sOut,
                                          const float* __restrict__ sGate,
                                          int e, int r0, int c0) {
    int ocb = c0 & 63;
    #pragma unroll
    for (int i = 0; i < 4; i++) {
        int m = r0 + i;
        #pragma unroll
        for (int j = 0; j < 4; j++) {
            float lo, hi;
            unpack2(acc[i][j], lo, hi);
            int oc = ocb + 2 * j;
            lo += sB3[c0 + 2 * j];
            hi += sB3[c0 + 2 * j + 1];
            if (e < 8) {                       // task expert: task t = e>>2, slot e&3
                int t   = e >> 2;
                float g = sGate[m * 16 + t * 8 + (e & 3)];
                float* o = sOut + t * 4096 + m * 64 + oc;
                o[0] += g * lo;
                o[1] += g * hi;
            } else {                           // shared expert: contributes to both tasks
                int s    = e - 8;
                float g0 = sGate[m * 16 + 4 + s];
                float g1 = sGate[m * 16 + 12 + s];
                float* o0 = sOut + m * 64 + oc;
                float* o1 = o0 + 4096;
                o0[0] += g0 * lo;  o0[1] += g0 * hi;
                o1[0] += g1 * lo;  o1[1] += g1 * hi;
            }
        }
    }
}

extern "C" __global__ void __launch_bounds__(NTHREADS, 1)
moe_fused(const float* __restrict__ X,
          const float* __restrict__ Wt1, const float* __restrict__ bt1,
          const float* __restrict__ Wt2, const float* __restrict__ bt2,
          const float* __restrict__ Wt3, const float* __restrict__ bt3,
          const float* __restrict__ Ws1, const float* __restrict__ bs1,
          const float* __restrict__ Ws2, const float* __restrict__ bs2,
          const float* __restrict__ Ws3, const float* __restrict__ bs3,
          const float* __restrict__ Wg,  const float* __restrict__ bg,
          float* __restrict__ Out)
{
    extern __shared__ float sm[];
    float* sX    = sm;                       // [64][260]
    float* sW    = sX    + 64 * SX_LDA;      // [64][128] (also stages Wg: 4096 fl)
    float* sH1   = sW    + 64 * 128;         // [64][132]
    float* sH2   = sH1   + 64 * SH_LDA;      // [64][132]
    float* sOut  = sH2   + 64 * SH_LDA;      // [2][64][64]
    float* sGate = sOut  + 2 * 64 * 64;      // [64][16]
    float* sB    = sGate + 64 * 16;          // [384] = b1|b2|b3 of current pair

    const int tid = threadIdx.x;
    const int bm  = blockIdx.x * M_TILE;

    // ---- load X tile (coalesced float4), zero accumulators, stage Wg ----
    #pragma unroll
    for (int i = 0; i < 16; i++) {
        int q = tid + i * NTHREADS;          // float4 index over 64x256
        int m = q >> 6, k4 = q & 63;
        float4 v = *(const float4*)(X + (size_t)(bm + m) * 256 + k4 * 4);
        *(float4*)(sX + m * SX_LDA + k4 * 4) = v;
    }
    for (int i = tid; i < 2 * 64 * 64; i += NTHREADS) sOut[i] = 0.f;
    #pragma unroll
    for (int i = 0; i < 4; i++)              // Wg: 2*256*8 = 1024 float4
        ((float4*)sW)[tid + i * NTHREADS] = ((const float4*)Wg)[tid + i * NTHREADS];
    __syncthreads();

    // ---- gates: one thread per (row, task), softmax over 8 logits ----
    if (tid < 128) {
        int m = tid >> 1, t = tid & 1;
        float lg[8];
        #pragma unroll
        for (int j = 0; j < 8; j++) lg[j] = bg[t * 8 + j];
        const float* wg = sW + t * 2048;     // [256][8]
        const float* xr = sX + m * SX_LDA;
        #pragma unroll 4
        for (int k = 0; k < 256; k++) {
            float x = xr[k];
            float4 w0 = *(const float4*)(wg + k * 8);
            float4 w1 = *(const float4*)(wg + k * 8 + 4);
            lg[0] += x * w0.x; lg[1] += x * w0.y; lg[2] += x * w0.z; lg[3] += x * w0.w;
            lg[4] += x * w1.x; lg[5] += x * w1.y; lg[6] += x * w1.z; lg[7] += x * w1.w;
        }
        float mx = lg[0];
        #pragma unroll
        for (int j = 1; j < 8; j++) mx = fmaxf(mx, lg[j]);
        float s = 0.f;
        #pragma unroll
        for (int j = 0; j < 8; j++) { lg[j] = __expf(lg[j] - mx); s += lg[j]; }
        float inv = 1.f / s;
        #pragma unroll
        for (int j = 0; j < 8; j++) sGate[m * 16 + t * 8 + j] = lg[j] * inv;
    }
    __syncthreads();

    const int tx = tid & 15, ty = tid >> 4;
    const int r0 = ty * 4, c0 = tx * 8;
    const int h  = (c0 >= 64) ? 1 : 0;       // which expert of the pair this thread owns

    for (int p = 0; p < 6; p++) {
        int e0 = p * 2;
        const float *W1a, *W1b, *W2a, *W2b, *W3a, *W3b;
        const float *B1a, *B1b, *B2a, *B2b, *B3a, *B3b;
        if (e0 < 8) {
            W1a = Wt1 + (size_t)e0 * 256 * 64; W1b = W1a + 256 * 64;
            W2a = Wt2 + (size_t)e0 * 64 * 64;  W2b = W2a + 64 * 64;
            W3a = Wt3 + (size_t)e0 * 64 * 64;  W3b = W3a + 64 * 64;
            B1a = bt1 + e0 * 64; B1b = B1a + 64;
            B2a = bt2 + e0 * 64; B2b = B2a + 64;
            B3a = bt3 + e0 * 64; B3b = B3a + 64;
        } else {
            int s = e0 - 8;
            W1a = Ws1 + (size_t)s * 256 * 64;  W1b = W1a + 256 * 64;
            W2a = Ws2 + (size_t)s * 64 * 64;   W2b = W2a + 64 * 64;
            W3a = Ws3 + (size_t)s * 64 * 64;   W3b = W3a + 64 * 64;
            B1a = bs1 + s * 64; B1b = B1a + 64;
            B2a = bs2 + s * 64; B2b = B2a + 64;
            B3a = bs3 + s * 64; B3b = B3a + 64;
        }

        // stage all three bias rows for the pair (read only after a later sync)
        if (tid < 128) {
            int hh = tid >> 6, cc = tid & 63;
            sB[tid]       = (hh ? B1b : B1a)[cc];
            sB[128 + tid] = (hh ? B2b : B2a)[cc];
            sB[256 + tid] = (hh ? B3b : B3a)[cc];
        }

        ull acc[4][4];
        // ---------------- Layer 1: [64,256] x [256,128] ----------------
        #pragma unroll
        for (int i = 0; i < 4; i++)
            #pragma unroll
            for (int j = 0; j < 4; j++) acc[i][j] = 0ull;
        for (int kk = 0; kk < 256; kk += 64) {
            stage_w(sW, W1a + kk * 64, W1b + kk * 64, tid);
            __syncthreads();
            mm_block(sX + kk, SX_LDA, sW, r0, c0, acc);
            __syncthreads();
        }
        epi_relu(acc, sB, sH1, r0, c0);

        // ---------------- Layer 2: block-diag [64,64] x [64,64] x2 ----------------
        stage_w(sW, W2a, W2b, tid);
        __syncthreads();
        #pragma unroll
        for (int i = 0; i < 4; i++)
            #pragma unroll
            for (int j = 0; j < 4; j++) acc[i][j] = 0ull;
        mm_block(sH1 + h * 64, SH_LDA, sW, r0, c0, acc);
        __syncthreads();
        epi_relu(acc, sB + 128, sH2, r0, c0);

        // ---------------- Layer 3 ----------------
        stage_w(sW, W3a, W3b, tid);
        __syncthreads();
        #pragma unroll
        for (int i = 0; i < 4; i++)
            #pragma unroll
            for (int j = 0; j < 4; j++) acc[i][j] = 0ull;
        mm_block(sH2 + h * 64, SH_LDA, sW, r0, c0, acc);

        // gated accumulation into sOut, two phases (the two pair-halves map onto
        // the same output columns — serialize them)
        int e = e0 + h;
        if (h == 0) accum_out(acc, sB + 256, sOut, sGate, e, r0, c0);
        __syncthreads();
        if (h == 1) accum_out(acc, sB + 256, sOut, sGate, e, r0, c0);
        __syncthreads();
    }

    // ---- writeback [64 rows][2 tasks][64] -> Out, coalesced float4 ----
    for (int q = tid; q < 2048; q += NTHREADS) {       // float4 units
        int m = q >> 5, rem = q & 31;
        int t = rem >> 4, oc4 = rem & 15;
        float4 v = *(const float4*)(sOut + t * 4096 + m * 64 + oc4 * 4);
        *(float4*)(Out + (size_t)(bm + m) * 128 + t * 64 + oc4 * 4) = v;
    }
}

extern "C" void kernel_launch(void* const* d_in, const int* in_sizes, int n_in,
                              void* d_out, int out_size) {
    const float* X   = (const float*)d_in[0];
    const float* Wt1 = (const float*)d_in[1];
    const float* bt1 = (const float*)d_in[2];
    const float* Wt2 = (const float*)d_in[3];
    const float* bt2 = (const float*)d_in[4];
    const float* Wt3 = (const float*)d_in[5];
    const float* bt3 = (const float*)d_in[6];
    const float* Ws1 = (const float*)d_in[7];
    const float* bs1 = (const float*)d_in[8];
    const float* Ws2 = (const float*)d_in[9];
    const float* bs2 = (const float*)d_in[10];
    const float* Ws3 = (const float*)d_in[11];
    const float* bs3 = (const float*)d_in[12];
    const float* Wg  = (const float*)d_in[13];
    const float* bg  = (const float*)d_in[14];
    float* Out = (float*)d_out;

    int B    = in_sizes[0] / 256;
    int grid = B / M_TILE;

    size_t smem = (size_t)(64 * SX_LDA + 64 * 128 + 2 * 64 * SH_LDA +
                           2 * 64 * 64 + 64 * 16 + 384) * sizeof(float);
    cudaFuncSetAttribute((const void*)moe_fused,
                         cudaFuncAttributeMaxDynamicSharedMemorySize, (int)smem);
    moe_fused<<<grid, NTHREADS, smem>>>(X, Wt1, bt1, Wt2, bt2, Wt3, bt3,
                                        Ws1, bs1, Ws2, bs2, Ws3, bs3, Wg, bg, Out);
}

// round 4
// speedup vs baseline: 2.8742x; 2.8742x over previous
#include <cuda_runtime.h>
#include <cuda_bf16.h>
#include <cstdint>

// ===========================================================================
// ExtractNet fused MoE via mma.sync bf16 (hi/lo 3-term split), sm_103-safe.
// B=65536, IN=256, H=64, 12 experts (8 task + 4 shared), 2 gated tasks.
// 1 CTA = 128 rows, 8 warps; warp w owns rows [16w, 16w+16) x all 64 cols.
// mma.sync.aligned.m16n8k16.row.col.f32.bf16.bf16.f32 + ldmatrix.
// A-side: X / hidden tiles [m][k] bf16, XOR-swizzled; B-side: W^T [n][k].
// ===========================================================================

#define NT 256
#define MT 128

// smem byte offsets
#define OFF_X    0u        // X: hi 65536 | lo 65536
#define OFF_SCR  131072u   // 81920-byte scratch: W1(64K) or H1(32K)+W23(16K)+H2(32K)
#define OFF_GATE 212992u   // 128 x 16 fp32 = 8192
#define SM_SIZE  221184u

// scratch sublayout
#define SCR_W1HI 0u
#define SCR_W1LO 32768u
#define SCR_H1HI 0u
#define SCR_H1LO 16384u
#define SCR_WHI  32768u    // W2 / W3: hi 8192 | lo 8192
#define SCR_WLO  40960u
#define SCR_H2HI 49152u
#define SCR_H2LO 65536u

// ---- device scratch: pre-split, transposed, pre-swizzled weights ----
__device__ __align__(16) __nv_bfloat16 g_W1hi[12 * 64 * 256];
__device__ __align__(16) __nv_bfloat16 g_W1lo[12 * 64 * 256];
__device__ __align__(16) __nv_bfloat16 g_W23hi[12 * 2 * 64 * 64];
__device__ __align__(16) __nv_bfloat16 g_W23lo[12 * 2 * 64 * 64];

// ---------------------------------------------------------------------------
__device__ __forceinline__ uint32_t smem_u32(const void* p) {
    uint32_t a;
    asm("{ .reg .u64 t; cvta.to.shared.u64 t, %1; cvt.u32.u64 %0, t; }" : "=r"(a) : "l"(p));
    return a;
}
__device__ __forceinline__ void ldsm4(uint32_t& r0, uint32_t& r1, uint32_t& r2,
                                      uint32_t& r3, uint32_t a) {
    asm volatile("ldmatrix.sync.aligned.m8n8.x4.shared.b16 {%0,%1,%2,%3}, [%4];"
                 : "=r"(r0), "=r"(r1), "=r"(r2), "=r"(r3) : "r"(a));
}
__device__ __forceinline__ void mma16816(float* c, uint32_t a0, uint32_t a1,
                                         uint32_t a2, uint32_t a3,
                                         uint32_t b0, uint32_t b1) {
    asm volatile(
        "mma.sync.aligned.m16n8k16.row.col.f32.bf16.bf16.f32 "
        "{%0,%1,%2,%3}, {%4,%5,%6,%7}, {%8,%9}, {%0,%1,%2,%3};"
        : "+f"(c[0]), "+f"(c[1]), "+f"(c[2]), "+f"(c[3])
        : "r"(a0), "r"(a1), "r"(a2), "r"(a3), "r"(b0), "r"(b1));
}
// hi/lo split of a float pair into packed bf16x2 words (low half = first elem)
__device__ __forceinline__ void split2(float a, float b, uint32_t& h, uint32_t& l) {
    __nv_bfloat16 ha = __float2bfloat16(a), hb = __float2bfloat16(b);
    __nv_bfloat16 la = __float2bfloat16(a - __bfloat162float(ha));
    __nv_bfloat16 lb = __float2bfloat16(b - __bfloat162float(hb));
    h = (uint32_t)__bfloat16_as_ushort(ha) | ((uint32_t)__bfloat16_as_ushort(hb) << 16);
    l = (uint32_t)__bfloat16_as_ushort(la) | ((uint32_t)__bfloat16_as_ushort(lb) << 16);
}

// swizzled byte offsets: XOR row low-3-bits into 16B-unit index (conflict-free ldmatrix)
__device__ __forceinline__ uint32_t xoff(int m, int k) {   // row stride 512B (K=256)
    return (uint32_t)(m * 512 + ((((k >> 3) ^ (m & 7)) << 4) | ((k & 7) << 1)));
}
__device__ __forceinline__ uint32_t hoff(int m, int k) {   // row stride 128B (K=64)
    return (uint32_t)(m * 128 + ((((k >> 3) ^ (m & 7)) << 4) | ((k & 7) << 1)));
}

// Warp GEMM: acc[8][4] += A[16m x 16K*KS] * B^T[64n x 16K*KS], 3-term split.
// aHi/aLo: smem addr of A row (w*16+lrow), bHi/bLo: smem addr of B row lrow.
template <int KS, int BST>
__device__ __forceinline__ void gemm_warp(uint32_t aHi, uint32_t aLo,
                                          uint32_t bHi, uint32_t bLo,
                                          int row7, int khalf, float (*acc)[4]) {
    #pragma unroll
    for (int ks = 0; ks < KS; ks++) {
        uint32_t u = (uint32_t)(((2 * ks + khalf) ^ row7) << 4);
        uint32_t ah0, ah1, ah2, ah3, al0, al1, al2, al3;
        ldsm4(ah0, ah1, ah2, ah3, aHi + u);
        ldsm4(al0, al1, al2, al3, aLo + u);
        #pragma unroll
        for (int p = 0; p < 4; p++) {
            uint32_t ub = (uint32_t)(p * 16 * BST) + u;
            uint32_t bh0, bh1, bh2, bh3, bl0, bl1, bl2, bl3;
            ldsm4(bh0, bh1, bh2, bh3, bHi + ub);
            ldsm4(bl0, bl1, bl2, bl3, bLo + ub);
            mma16816(acc[2 * p],     ah0, ah1, ah2, ah3, bh0, bh2);
            mma16816(acc[2 * p + 1], ah0, ah1, ah2, ah3, bh1, bh3);
            mma16816(acc[2 * p],     ah0, ah1, ah2, ah3, bl0, bl2);
            mma16816(acc[2 * p + 1], ah0, ah1, ah2, ah3, bl1, bl3);
            mma16816(acc[2 * p],     al0, al1, al2, al3, bh0, bh2);
            mma16816(acc[2 * p + 1], al0, al1, al2, al3, bh1, bh3);
        }
    }
}

// epilogue: bias + relu + split -> swizzled hidden tile (stride 128B)
__device__ __forceinline__ void epilogue(float (*acc)[4], const float* __restrict__ bias,
                                         char* S, uint32_t dHi, uint32_t dLo,
                                         int w, int lane) {
    int g = lane >> 2, t4 = lane & 3;
    int m0 = w * 16 + g, m1 = m0 + 8;
    #pragma unroll
    for (int nt = 0; nt < 8; nt++) {
        int col = nt * 8 + t4 * 2;
        float bx = bias[col], by = bias[col + 1];
        float v00 = fmaxf(acc[nt][0] + bx, 0.f);
        float v01 = fmaxf(acc[nt][1] + by, 0.f);
        float v10 = fmaxf(acc[nt][2] + bx, 0.f);
        float v11 = fmaxf(acc[nt][3] + by, 0.f);
        uint32_t h0, l0, h1, l1;
        split2(v00, v01, h0, l0);
        split2(v10, v11, h1, l1);
        uint32_t o0 = hoff(m0, col), o1 = hoff(m1, col);
        *(uint32_t*)(S + dHi + o0) = h0;
        *(uint32_t*)(S + dLo + o0) = l0;
        *(uint32_t*)(S + dHi + o1) = h1;
        *(uint32_t*)(S + dLo + o1) = l1;
    }
}

// ===========================================================================
// prep kernel: split + transpose + swizzle weights into bf16 hi/lo scratch
// ===========================================================================
extern "C" __global__ void prep_w(const float* __restrict__ Wt1, const float* __restrict__ Wt2,
                                  const float* __restrict__ Wt3, const float* __restrict__ Ws1,
                                  const float* __restrict__ Ws2, const float* __restrict__ Ws3) {
    int idx = blockIdx.x * blockDim.x + threadIdx.x;
    const int N1 = 12 * 64 * 256;
    const int N2 = 12 * 2 * 64 * 64;
    if (idx < N1) {
        int e = idx >> 14, rem = idx & 16383;
        int n = rem >> 8, k = rem & 255;
        float v = (e < 8) ? Wt1[((size_t)e * 256 + k) * 64 + n]
                          : Ws1[((size_t)(e - 8) * 256 + k) * 64 + n];
        __nv_bfloat16 h = __float2bfloat16(v);
        __nv_bfloat16 l = __float2bfloat16(v - __bfloat162float(h));
        int d = e * 16384 + n * 256 + (((k >> 3) ^ (n & 7)) << 3) + (k & 7);
        g_W1hi[d] = h;
        g_W1lo[d] = l;
    } else if (idx < N1 + N2) {
        int j = idx - N1;
        int e = j >> 13, rem = j & 8191;
        int ly = rem >> 12, r = rem & 4095;
        int n = r >> 6, k = r & 63;
        float v;
        if (ly == 0) v = (e < 8) ? Wt2[((size_t)e * 64 + k) * 64 + n]
                                 : Ws2[((size_t)(e - 8) * 64 + k) * 64 + n];
        else         v = (e < 8) ? Wt3[((size_t)e * 64 + k) * 64 + n]
                                 : Ws3[((size_t)(e - 8) * 64 + k) * 64 + n];
        __nv_bfloat16 h = __float2bfloat16(v);
        __nv_bfloat16 l = __float2bfloat16(v - __bfloat162float(h));
        int d = (e * 2 + ly) * 4096 + n * 64 + (((k >> 3) ^ (n & 7)) << 3) + (k & 7);
        g_W23hi[d] = h;
        g_W23lo[d] = l;
    }
}

// ===========================================================================
// main kernel
// ===========================================================================
extern "C" __global__ void __launch_bounds__(NT, 1)
moe_mma(const float* __restrict__ X,
        const float* __restrict__ bt1, const float* __restrict__ bt2,
        const float* __restrict__ bt3, const float* __restrict__ bs1,
        const float* __restrict__ bs2, const float* __restrict__ bs3,
        const float* __restrict__ Wg,  const float* __restrict__ bg,
        float* __restrict__ Out)
{
    extern __shared__ __align__(16) char S[];
    const uint32_t SB = smem_u32(S);
    const int tid  = threadIdx.x;
    const int bm   = blockIdx.x * MT;
    const int w    = tid >> 5, lane = tid & 31;
    const int lrow = lane & 15, khalf = lane >> 4;
    const int row7 = lrow & 7;
    float* sGate = (float*)(S + OFF_GATE);

    // ---- stage Wg into scratch, compute exact fp32 gates ----
    #pragma unroll
    for (int i = 0; i < 4; i++)
        ((float4*)(S + OFF_SCR))[tid + i * NT] = ((const float4*)Wg)[tid + i * NT];
    __syncthreads();
    {
        int m = tid >> 1, t = tid & 1;
        const float* wg = (const float*)(S + OFF_SCR) + t * 2048;
        const float* xr = X + (size_t)(bm + m) * 256;
        float lg[8];
        #pragma unroll
        for (int j = 0; j < 8; j++) lg[j] = bg[t * 8 + j];
        for (int k = 0; k < 256; k++) {
            float x = __ldg(xr + k);
            float4 w0 = *(const float4*)(wg + k * 8);
            float4 w1 = *(const float4*)(wg + k * 8 + 4);
            lg[0] += x * w0.x; lg[1] += x * w0.y; lg[2] += x * w0.z; lg[3] += x * w0.w;
            lg[4] += x * w1.x; lg[5] += x * w1.y; lg[6] += x * w1.z; lg[7] += x * w1.w;
        }
        float mx = lg[0];
        #pragma unroll
        for (int j = 1; j < 8; j++) mx = fmaxf(mx, lg[j]);
        float s = 0.f;
        #pragma unroll
        for (int j = 0; j < 8; j++) { lg[j] = __expf(lg[j] - mx); s += lg[j]; }
        float inv = 1.f / s;
        #pragma unroll
        for (int j = 0; j < 8; j++) sGate[m * 16 + t * 8 + j] = lg[j] * inv;
    }

    // ---- stage X: fp32 -> hi/lo bf16, swizzled [128][256] ----
    #pragma unroll
    for (int i = 0; i < 32; i++) {
        int q = tid + i * NT;             // 0..8191 float4 units
        int m = q >> 6, k = (q & 63) * 4;
        float4 x = *(const float4*)(X + (size_t)(bm + m) * 256 + k);
        uint32_t h0, l0, h1, l1;
        split2(x.x, x.y, h0, l0);
        split2(x.z, x.w, h1, l1);
        uint32_t o = xoff(m, k);
        *(uint2*)(S + OFF_X + o)          = make_uint2(h0, h1);
        *(uint2*)(S + OFF_X + 65536u + o) = make_uint2(l0, l1);
    }

    float tacc0[8][4], tacc1[8][4];
    #pragma unroll
    for (int nt = 0; nt < 8; nt++)
        #pragma unroll
        for (int j = 0; j < 4; j++) { tacc0[nt][j] = 0.f; tacc1[nt][j] = 0.f; }

    const uint32_t aX_hi = SB + OFF_X + (uint32_t)((w * 16 + lrow) * 512);
    const uint32_t aX_lo = aX_hi + 65536u;
    const uint32_t aH_row128 = (uint32_t)((w * 16 + lrow) * 128);
    const uint32_t bRow128   = (uint32_t)(lrow * 128);
    const uint32_t bRow512   = (uint32_t)(lrow * 512);

    for (int e = 0; e < 12; e++) {
        const float* b1p = (e < 8) ? bt1 + e * 64 : bs1 + (e - 8) * 64;
        const float* b2p = (e < 8) ? bt2 + e * 64 : bs2 + (e - 8) * 64;
        const float* b3p = (e < 8) ? bt3 + e * 64 : bs3 + (e - 8) * 64;

        float acc[8][4];

        // ---- stage W1 (pre-swizzled raw copy) ----
        __syncthreads();   // scratch free (prev expert's reads done / gate reads done)
        {
            const uint4* sH = (const uint4*)(g_W1hi + e * 16384);
            const uint4* sL = (const uint4*)(g_W1lo + e * 16384);
            #pragma unroll
            for (int i = 0; i < 8; i++) {
                int j = tid + i * NT;      // 0..2047
                ((uint4*)(S + OFF_SCR + SCR_W1HI))[j] = sH[j];
                ((uint4*)(S + OFF_SCR + SCR_W1LO))[j] = sL[j];
            }
        }
        __syncthreads();

        // ---- layer 1: [128,256] x [256,64] ----
        #pragma unroll
        for (int nt = 0; nt < 8; nt++)
            #pragma unroll
            for (int j = 0; j < 4; j++) acc[nt][j] = 0.f;
        gemm_warp<16, 512>(aX_hi, aX_lo,
                           SB + OFF_SCR + SCR_W1HI + bRow512,
                           SB + OFF_SCR + SCR_W1LO + bRow512,
                           row7, khalf, acc);
        __syncthreads();   // W1 reads done; H1/W2 overwrite scratch

        epilogue(acc, b1p, S, OFF_SCR + SCR_H1HI, OFF_SCR + SCR_H1LO, w, lane);
        {
            const uint4* sH = (const uint4*)(g_W23hi + (e * 2 + 0) * 4096);
            const uint4* sL = (const uint4*)(g_W23lo + (e * 2 + 0) * 4096);
            #pragma unroll
            for (int i = 0; i < 2; i++) {
                int j = tid + i * NT;      // 0..511
                ((uint4*)(S + OFF_SCR + SCR_WHI))[j] = sH[j];
                ((uint4*)(S + OFF_SCR + SCR_WLO))[j] = sL[j];
            }
        }
        __syncthreads();

        // ---- layer 2: [128,64] x [64,64] ----
        #pragma unroll
        for (int nt = 0; nt < 8; nt++)
            #pragma unroll
            for (int j = 0; j < 4; j++) acc[nt][j] = 0.f;
        gemm_warp<4, 128>(SB + OFF_SCR + SCR_H1HI + aH_row128,
                          SB + OFF_SCR + SCR_H1LO + aH_row128,
                          SB + OFF_SCR + SCR_WHI + bRow128,
                          SB + OFF_SCR + SCR_WLO + bRow128,
                          row7, khalf, acc);
        __syncthreads();   // W2 reads done; W3 overwrites

        epilogue(acc, b2p, S, OFF_SCR + SCR_H2HI, OFF_SCR + SCR_H2LO, w, lane);
        {
            const uint4* sH = (const uint4*)(g_W23hi + (e * 2 + 1) * 4096);
            const uint4* sL = (const uint4*)(g_W23lo + (e * 2 + 1) * 4096);
            #pragma unroll
            for (int i = 0; i < 2; i++) {
                int j = tid + i * NT;
                ((uint4*)(S + OFF_SCR + SCR_WHI))[j] = sH[j];
                ((uint4*)(S + OFF_SCR + SCR_WLO))[j] = sL[j];
            }
        }
        __syncthreads();

        // ---- layer 3: [128,64] x [64,64] ----
        #pragma unroll
        for (int nt = 0; nt < 8; nt++)
            #pragma unroll
            for (int j = 0; j < 4; j++) acc[nt][j] = 0.f;
        gemm_warp<4, 128>(SB + OFF_SCR + SCR_H2HI + aH_row128,
                          SB + OFF_SCR + SCR_H2LO + aH_row128,
                          SB + OFF_SCR + SCR_WHI + bRow128,
                          SB + OFF_SCR + SCR_WLO + bRow128,
                          row7, khalf, acc);

        // ---- gated accumulation ----
        {
            int g = lane >> 2, t4 = lane & 3;
            int m0 = w * 16 + g, m1 = m0 + 8;
            if (e < 8) {
                int t = e >> 2;
                float g0 = sGate[m0 * 16 + t * 8 + (e & 3)];
                float g1 = sGate[m1 * 16 + t * 8 + (e & 3)];
                float (*ta)[4] = t ? tacc1 : tacc0;
                #pragma unroll
                for (int nt = 0; nt < 8; nt++) {
                    int col = nt * 8 + t4 * 2;
                    float bx = b3p[col], by = b3p[col + 1];
                    ta[nt][0] += g0 * (acc[nt][0] + bx);
                    ta[nt][1] += g0 * (acc[nt][1] + by);
                    ta[nt][2] += g1 * (acc[nt][2] + bx);
                    ta[nt][3] += g1 * (acc[nt][3] + by);
                }
            } else {
                int s = e - 8;
                float g00 = sGate[m0 * 16 + 4 + s],  g01 = sGate[m0 * 16 + 12 + s];
                float g10 = sGate[m1 * 16 + 4 + s],  g11 = sGate[m1 * 16 + 12 + s];
                #pragma unroll
                for (int nt = 0; nt < 8; nt++) {
                    int col = nt * 8 + t4 * 2;
                    float bx = b3p[col], by = b3p[col + 1];
                    float v0 = acc[nt][0] + bx, v1 = acc[nt][1] + by;
                    float v2 = acc[nt][2] + bx, v3 = acc[nt][3] + by;
                    tacc0[nt][0] += g00 * v0; tacc0[nt][1] += g00 * v1;
                    tacc0[nt][2] += g10 * v2; tacc0[nt][3] += g10 * v3;
                    tacc1[nt][0] += g01 * v0; tacc1[nt][1] += g01 * v1;
                    tacc1[nt][2] += g11 * v2; tacc1[nt][3] += g11 * v3;
                }
            }
        }
    }

    // ---- writeback straight from registers (float2 stores, quad-contiguous) ----
    {
        int g = lane >> 2, t4 = lane & 3;
        int m0 = bm + w * 16 + g, m1 = m0 + 8;
        #pragma unroll
        for (int nt = 0; nt < 8; nt++) {
            int col = nt * 8 + t4 * 2;
            *(float2*)(Out + (size_t)m0 * 128 + col)      = make_float2(tacc0[nt][0], tacc0[nt][1]);
            *(float2*)(Out + (size_t)m1 * 128 + col)      = make_float2(tacc0[nt][2], tacc0[nt][3]);
            *(float2*)(Out + (size_t)m0 * 128 + 64 + col) = make_float2(tacc1[nt][0], tacc1[nt][1]);
            *(float2*)(Out + (size_t)m1 * 128 + 64 + col) = make_float2(tacc1[nt][2], tacc1[nt][3]);
        }
    }
}

// ===========================================================================
extern "C" void kernel_launch(void* const* d_in, const int* in_sizes, int n_in,
                              void* d_out, int out_size) {
    const float* X   = (const float*)d_in[0];
    const float* Wt1 = (const float*)d_in[1];
    const float* bt1 = (const float*)d_in[2];
    const float* Wt2 = (const float*)d_in[3];
    const float* bt2 = (const float*)d_in[4];
    const float* Wt3 = (const float*)d_in[5];
    const float* bt3 = (const float*)d_in[6];
    const float* Ws1 = (const float*)d_in[7];
    const float* bs1 = (const float*)d_in[8];
    const float* Ws2 = (const float*)d_in[9];
    const float* bs2 = (const float*)d_in[10];
    const float* Ws3 = (const float*)d_in[11];
    const float* bs3 = (const float*)d_in[12];
    const float* Wg  = (const float*)d_in[13];
    const float* bg  = (const float*)d_in[14];
    float* Out = (float*)d_out;

    int B = in_sizes[0] / 256;
    int grid = B / MT;

    prep_w<<<1152, 256>>>(Wt1, Wt2, Wt3, Ws1, Ws2, Ws3);

    cudaFuncSetAttribute((const void*)moe_mma,
                         cudaFuncAttributeMaxDynamicSharedMemorySize, (int)SM_SIZE);
    moe_mma<<<grid, NT, SM_SIZE>>>(X, bt1, bt2, bt3, bs1, bs2, bs3, Wg, bg, Out);
}